// round 17
// baseline (speedup 1.0000x reference)
#include <cuda_runtime.h>

// DMTSkeletonize: exact squared-EDT + 3x3x3 local-max skeleton on d^2.
// Pass 1 (binary input): nearest-zero via warp shuffle scans (exact).
// Passes 2/3: adaptive min-plus transform; DYNAMIC break checked once per
//   4-k group (extra in-group terms are genuine candidates computed exactly
//   as the reference; the break only skips terms k^2 >= running-min which
//   cannot lower the min since f >= 0). All finite values are integers < 2^24
//   so every kept term is bit-identical to the reference's.
// Shapes: img [4,1,160,160,160] fp32. B=4, D=H=W=160.

#define WW    160
#define HWSZ  25600      // H*W
#define DHWSZ 4096000    // D*H*W
#define NTOT  16384000   // B*D*H*W
#define FINF  1e12f
#define NEGINF (-3.0e38f)

// Scratch (device globals — no allocation anywhere, per harness rules)
__device__ float g_A[NTOT];
__device__ float g_B[NTOT];

// ---------------------------------------------------------------------------
// EDT 1D pass. MODE 0: x lines (img binarized -> g_A), scan-based.
// MODE 1: y lines (stride W), g_A -> g_B.  MODE 2: z lines (stride HW), g_B->g_A.
// 512 threads, 32 lines/block.
// ---------------------------------------------------------------------------
template <int MODE>
__global__ __launch_bounds__(512) void edt_pass_kernel(const float* __restrict__ img)
{
    __shared__ float fsh[32][161];  // pad: conflict-free transposed access

    const float* __restrict__ in  = (MODE == 0) ? img : (MODE == 1 ? g_A : g_B);
    float* __restrict__       out = (MODE == 1) ? g_B : g_A;

    const int tid = threadIdx.x;
    const int bid = blockIdx.x;

    long base;
    int stride;
    if (MODE == 0) {
        base = (long)bid * (32 * 160);
        stride = 1;
    } else if (MODE == 1) {
        int p  = bid / 5;            // p = b*160 + z
        int x0 = (bid % 5) * 32;
        base = (long)p * HWSZ + x0;
        stride = WW;
    } else {
        int p  = bid / 5;            // p = b*160 + y
        int x0 = (bid % 5) * 32;
        int b = p / 160, y = p - b * 160;
        base = (long)b * DHWSZ + (long)y * WW + x0;
        stride = HWSZ;
    }

    // ---- load tile into shared (coalesced) ----
    if (MODE == 0) {
        for (int idx = tid; idx < 32 * 160; idx += 512) {
            int l = idx / 160;
            int j = idx - l * 160;
            float v = in[base + idx];
            fsh[l][j] = (v > 0.5f) ? 0.0f : FINF;     // binarize + invert
        }
    } else {
        for (int idx = tid; idx < 32 * 160; idx += 512) {
            int j = idx >> 5;
            int l = idx & 31;
            fsh[l][j] = in[base + (long)j * stride + l];
        }
    }
    __syncthreads();

    if (MODE == 0) {
        // ---- scan-based nearest-zero: warp = 2 lines, lane = 5-elem chunk ----
        const int warp = tid >> 5;       // 0..15
        const int lane = tid & 31;
#pragma unroll 1
        for (int li = 0; li < 2; li++) {
            const int l = warp * 2 + li;
            float* __restrict__ f = fsh[l];
            const int p0 = 5 * lane;

            float v[5];
#pragma unroll
            for (int c = 0; c < 5; c++) v[c] = f[p0 + c];

            // forward: position of last zero-site (f==0) at or before p
            int lane_last = -1000;
#pragma unroll
            for (int c = 0; c < 5; c++) if (v[c] == 0.0f) lane_last = p0 + c;
            int incl = lane_last;
#pragma unroll
            for (int off = 1; off < 32; off <<= 1) {
                int o = __shfl_up_sync(0xFFFFFFFFu, incl, off);
                if (lane >= off) incl = max(incl, o);
            }
            int excl = __shfl_up_sync(0xFFFFFFFFu, incl, 1);
            if (lane == 0) excl = -1000;

            // backward: position of first zero-site at or after p
            int lane_first = 1000;
#pragma unroll
            for (int c = 4; c >= 0; c--) if (v[c] == 0.0f) lane_first = p0 + c;
            int inclb = lane_first;
#pragma unroll
            for (int off = 1; off < 32; off <<= 1) {
                int o = __shfl_down_sync(0xFFFFFFFFu, inclb, off);
                if (lane + off < 32) inclb = min(inclb, o);
            }
            int exclb = __shfl_down_sync(0xFFFFFFFFu, inclb, 1);
            if (lane == 31) exclb = 1000;

            int nzArr[5];
            int run_nz = exclb;
#pragma unroll
            for (int c = 4; c >= 0; c--) {
                if (v[c] == 0.0f) run_nz = p0 + c;
                nzArr[c] = run_nz;
            }
            int run_lz = excl;
#pragma unroll
            for (int c = 0; c < 5; c++) {
                int p = p0 + c;
                if (v[c] == 0.0f) run_lz = p;
                int d = min(p - run_lz, nzArr[c] - p);
                // writes only this lane's own chunk; no cross-lane readers
                f[p] = (d >= 160) ? FINF : (float)(d * d);
            }
        }
        __syncthreads();
    } else {
        // ---- adaptive min-plus, 2 chains (i, i+5), break per 4-k group ----
        const int l = tid >> 4;          // line 0..31
        const int s = tid & 15;          // segment 0..15 (10 outputs each)
        const float* __restrict__ f = fsh[l];

        float res[10];
#pragma unroll 1
        for (int o = 0; o < 5; o++) {
            const int i1 = s * 10 + o;
            const int i2 = i1 + 5;
            float a1 = f[i1];            // j = i term: exact
            float a2 = f[i2];
#pragma unroll 1
            for (int k = 1; k < 160; k += 4) {
                // dynamic group-entry break: for all k' >= k, k'^2 >= k^2;
                // if k^2 >= max(a1,a2), no further term can lower either min.
                const float kk0 = (float)(k * k);
                if (kk0 >= fmaxf(a1, a2)) break;
#pragma unroll
                for (int d = 0; d < 4; d++) {
                    const int kd = k + d;
                    if (kd < 160) {
                        const float kk = (float)(kd * kd);     // exact fp32
                        int jn1 = i1 - kd, jp1 = i1 + kd;
                        if (jn1 >= 0)  a1 = fminf(a1, kk + f[jn1]);  // 1 rounding
                        if (jp1 < 160) a1 = fminf(a1, kk + f[jp1]);
                        int jn2 = i2 - kd, jp2 = i2 + kd;
                        if (jn2 >= 0)  a2 = fminf(a2, kk + f[jn2]);
                        if (jp2 < 160) a2 = fminf(a2, kk + f[jp2]);
                    }
                }
            }
            res[o] = a1;
            res[o + 5] = a2;
        }

        __syncthreads();   // all reads of fsh done before overwrite
#pragma unroll
        for (int o = 0; o < 10; o++) fsh[l][s * 10 + o] = res[o];
        __syncthreads();
    }

    // ---- coalesced store ----
    if (MODE == 0) {
        for (int idx = tid; idx < 32 * 160; idx += 512) {
            int ll = idx / 160;
            int j  = idx - ll * 160;
            out[base + idx] = fsh[ll][j];
        }
    } else {
        for (int idx = tid; idx < 32 * 160; idx += 512) {
            int j  = idx >> 5;
            int ll = idx & 31;
            out[base + (long)j * stride + ll] = fsh[ll][j];
        }
    }
}

// ---------------------------------------------------------------------------
// Fused 3x3x3 max + skeleton + multiply. Software-pipelined z-march.
// [Best-measured variant, stable at ~86.5us — unchanged]
// ---------------------------------------------------------------------------
#define SLICE_ELEMS 1156           // 34*34
#define SROW 36                    // padded row
#define SBUF (34 * SROW)

__global__ __launch_bounds__(256) void skel_kernel(const float* __restrict__ img,
                                                   float* __restrict__ out)
{
    __shared__ float sA[2 * SBUF];

    const int tid = threadIdx.x;
    const int tx  = tid & 31;
    const int ty  = tid >> 5;                // 0..7
    const int x0  = blockIdx.x * 32;
    const int y0  = blockIdx.y * 32;
    const int b   = blockIdx.z >> 4;         // 0..3
    const int z0  = (blockIdx.z & 15) * 10;  // 0..150
    const long gbase = (long)b * DHWSZ;
    const float* __restrict__ A = g_A + gbase;

    // ---- hoisted halo-load bookkeeping (loop-invariant) ----
    int  gofs[5];
    int  sofs[5];
    bool inb[5];
#pragma unroll
    for (int r = 0; r < 5; r++) {
        int idx = tid + 256 * r;
        bool it_ok = idx < SLICE_ELEMS;
        int hy = idx / 34;
        int hx = idx - hy * 34;
        int gx = x0 + hx - 1, gy = y0 + hy - 1;
        inb[r]  = it_ok && gx >= 0 && gx < 160 && gy >= 0 && gy < 160;
        gofs[r] = gy * WW + gx;
        sofs[r] = it_ok ? (hy * SROW + hx) : -1;
    }

    float v[5];
    {
        const bool zok = (z0 - 1) >= 0;
        const float* __restrict__ S = A + (long)(z0 - 1) * HWSZ;
#pragma unroll
        for (int r = 0; r < 5; r++)
            v[r] = (zok && inb[r]) ? S[gofs[r]] : NEGINF;
    }

    float xa[4], xb[4];
    float ch[4];
#pragma unroll
    for (int s_ = 0; s_ < 4; s_++) { xa[s_] = NEGINF; xb[s_] = NEGINF; ch[s_] = 0.0f; }

#pragma unroll 1
    for (int it = 0; it < 12; it++) {
        const int zs = z0 - 1 + it;
        float* __restrict__ buf = sA + (it & 1) * SBUF;

#pragma unroll
        for (int r = 0; r < 5; r++)
            if (sofs[r] >= 0) buf[sofs[r]] = v[r];
        __syncthreads();

        {
            const int zs2 = zs + 1;
            const bool zok2 = zs2 < 160;
            const float* __restrict__ S2 = A + (long)zs2 * HWSZ;
#pragma unroll
            for (int r = 0; r < 5; r++)
                v[r] = (zok2 && inb[r]) ? S2[gofs[r]] : NEGINF;
        }

#pragma unroll
        for (int s_ = 0; s_ < 4; s_++) {
            const int hy = ty + 8 * s_ + 1;
            const float* row0 = buf + (hy - 1) * SROW + tx;
            const float* row1 = buf + hy * SROW + tx;
            const float* row2 = buf + (hy + 1) * SROW + tx;
            float m0 = fmaxf(fmaxf(row0[0], row0[1]), row0[2]);
            float c  = row1[1];
            float m1 = fmaxf(fmaxf(row1[0], c), row1[2]);
            float m2 = fmaxf(fmaxf(row2[0], row2[1]), row2[2]);
            float xn = fmaxf(fmaxf(m0, m1), m2);

            if (it >= 2) {
                float m = fmaxf(fmaxf(xa[s_], xb[s_]), xn);
                float cc = ch[s_];
                long gi = gbase + (long)(zs - 1) * HWSZ + (y0 + ty + 8 * s_) * WW + (x0 + tx);
                out[gi] = (cc >= m && cc > 0.0f) ? img[gi] : 0.0f;
            }
            xa[s_] = xb[s_];
            xb[s_] = xn;
            ch[s_] = c;
        }
        // single barrier per slice safe: STS to this buf at it+2 follows
        // sync(it+1), which follows all compute(it) reads.
    }
}

// ---------------------------------------------------------------------------
extern "C" void kernel_launch(void* const* d_in, const int* in_sizes, int n_in,
                              void* d_out, int out_size)
{
    const float* img = (const float*)d_in[0];
    float* out = (float*)d_out;

    // EDT: x -> y -> z  (g_A holds final d^2)
    edt_pass_kernel<0><<<3200, 512>>>(img);
    edt_pass_kernel<1><<<3200, 512>>>(nullptr);
    edt_pass_kernel<2><<<3200, 512>>>(nullptr);

    // Fused 3x3x3 max + skeleton + multiply (pipelined z-march)
    skel_kernel<<<dim3(5, 5, 64), 256>>>(img, out);
}